// round 1
// baseline (speedup 1.0000x reference)
#include <cuda_runtime.h>
#include <math.h>

#define MAXN 50000
#define MAXE 800000
#define NF 256

// ---------------- scratch (device globals; no allocation allowed) ----------
__device__ float g_h[(size_t)MAXN * NF];     // GEMM output (pre-aggregation features)
__device__ float g_buf[(size_t)MAXN * NF];   // layer output (post LN+ELU) = next layer input
__device__ float g_asrc[MAXN * 4];
__device__ float g_adst[MAXN * 4];
__device__ int   g_cnt[MAXN];
__device__ int   g_rowptr[MAXN + 1];
__device__ int   g_cursor[MAXN];
__device__ int   g_colsrc[MAXE];

// ---------------- CSR build ------------------------------------------------
__global__ void zero_cnt_kernel(int* __restrict__ cnt, int n) {
    int t = blockIdx.x * blockDim.x + threadIdx.x;
    if (t < n) cnt[t] = 0;
}

__global__ void hist_kernel(const int* __restrict__ dst, int* __restrict__ cnt, int e) {
    int t = blockIdx.x * blockDim.x + threadIdx.x;
    if (t < e) atomicAdd(&cnt[dst[t]], 1);
}

__global__ void scan_kernel(const int* __restrict__ cnt, int* __restrict__ rowptr,
                            int* __restrict__ cursor, int n) {
    __shared__ int sh[1024];
    int tid = threadIdx.x;
    int chunk = (n + 1023) >> 10;
    int base = tid * chunk;
    int s = 0;
    for (int j = 0; j < chunk; j++) {
        int idx = base + j;
        if (idx < n) s += cnt[idx];
    }
    sh[tid] = s;
    __syncthreads();
    for (int off = 1; off < 1024; off <<= 1) {
        int v = (tid >= off) ? sh[tid - off] : 0;
        __syncthreads();
        sh[tid] += v;
        __syncthreads();
    }
    int run = sh[tid] - s;  // exclusive prefix
    for (int j = 0; j < chunk; j++) {
        int idx = base + j;
        if (idx < n) {
            rowptr[idx] = run;
            cursor[idx] = run;
            run += cnt[idx];
        }
    }
    if (tid == 1023) rowptr[n] = run;
}

__global__ void scatter_kernel(const int* __restrict__ src, const int* __restrict__ dst,
                               int* __restrict__ cursor, int* __restrict__ colsrc, int e) {
    int t = blockIdx.x * blockDim.x + threadIdx.x;
    if (t < e) {
        int d = dst[t];
        int p = atomicAdd(&cursor[d], 1);
        colsrc[p] = src[t];
    }
}

// ---------------- GEMM: C[M,256] = A[M,K] @ B[K,256] -----------------------
// 128x128 block tile, BK=8, 256 threads, 8x8 per thread.
__global__ void __launch_bounds__(256) gemm_kernel(
    const float* __restrict__ A, const float* __restrict__ B,
    float* __restrict__ C, int M, int K)
{
    const int BM = 128, BN = 128, BK = 8;
    __shared__ float As[BK][BM + 4];
    __shared__ float Bs[BK][BN + 4];
    int tid = threadIdx.x;
    int row0 = blockIdx.y * BM;
    int col0 = blockIdx.x * BN;
    int tx = tid & 15;
    int ty = tid >> 4;
    int a_r = tid >> 1;
    int a_c = (tid & 1) << 2;
    int b_r = tid >> 5;
    int b_c = (tid & 31) << 2;

    float acc[8][8];
#pragma unroll
    for (int m = 0; m < 8; m++)
#pragma unroll
        for (int nn = 0; nn < 8; nn++) acc[m][nn] = 0.f;

    bool a_ok = (row0 + a_r) < M;
    const float* Aptr = A + (size_t)(row0 + a_r) * K + a_c;
    const float* Bptr = B + (size_t)b_r * NF + col0 + b_c;

    for (int kt = 0; kt < K; kt += BK) {
        float4 av = a_ok ? *reinterpret_cast<const float4*>(Aptr + kt)
                         : make_float4(0.f, 0.f, 0.f, 0.f);
        As[a_c + 0][a_r] = av.x;
        As[a_c + 1][a_r] = av.y;
        As[a_c + 2][a_r] = av.z;
        As[a_c + 3][a_r] = av.w;
        float4 bv = *reinterpret_cast<const float4*>(Bptr + (size_t)kt * NF);
        *reinterpret_cast<float4*>(&Bs[b_r][b_c]) = bv;
        __syncthreads();
#pragma unroll
        for (int k = 0; k < BK; k++) {
            float ra[8], rb[8];
            *reinterpret_cast<float4*>(&ra[0]) = *reinterpret_cast<const float4*>(&As[k][ty * 8]);
            *reinterpret_cast<float4*>(&ra[4]) = *reinterpret_cast<const float4*>(&As[k][ty * 8 + 4]);
            *reinterpret_cast<float4*>(&rb[0]) = *reinterpret_cast<const float4*>(&Bs[k][tx * 8]);
            *reinterpret_cast<float4*>(&rb[4]) = *reinterpret_cast<const float4*>(&Bs[k][tx * 8 + 4]);
#pragma unroll
            for (int m = 0; m < 8; m++)
#pragma unroll
                for (int nn = 0; nn < 8; nn++)
                    acc[m][nn] += ra[m] * rb[nn];
        }
        __syncthreads();
    }
#pragma unroll
    for (int m = 0; m < 8; m++) {
        int grow = row0 + ty * 8 + m;
        if (grow < M) {
            float4 v0 = make_float4(acc[m][0], acc[m][1], acc[m][2], acc[m][3]);
            float4 v1 = make_float4(acc[m][4], acc[m][5], acc[m][6], acc[m][7]);
            *reinterpret_cast<float4*>(&C[(size_t)grow * NF + col0 + tx * 8]) = v0;
            *reinterpret_cast<float4*>(&C[(size_t)grow * NF + col0 + tx * 8 + 4]) = v1;
        }
    }
}

// ---------------- alpha projections: asrc/adst[i,h] = sum_c h[i,h,c]*a[h,c] -
template <int H>
__global__ void __launch_bounds__(256) alpha_kernel(
    const float* __restrict__ hfeat,
    const float* __restrict__ a_s, const float* __restrict__ a_d,
    float* __restrict__ asrc, float* __restrict__ adst)
{
    const int C = NF / H;
    int i = blockIdx.x;
    int c = threadIdx.x;
    float hv = hfeat[(size_t)i * NF + c];
    float ps = hv * a_s[c];
    float pd = hv * a_d[c];
#pragma unroll
    for (int o = 16; o > 0; o >>= 1) {
        ps += __shfl_xor_sync(0xffffffffu, ps, o);
        pd += __shfl_xor_sync(0xffffffffu, pd, o);
    }
    __shared__ float ss[8], sd[8];
    int wid = c >> 5;
    if ((c & 31) == 0) { ss[wid] = ps; sd[wid] = pd; }
    __syncthreads();
    if (c < H) {
        const int wph = C >> 5;  // warps per head
        float rs = 0.f, rd = 0.f;
#pragma unroll
        for (int w = 0; w < wph; w++) { rs += ss[c * wph + w]; rd += sd[c * wph + w]; }
        asrc[i * H + c] = rs;
        adst[i * H + c] = rd;
    }
}

// ---------------- block-sum helper -----------------------------------------
__device__ __forceinline__ float block_sum256(float v, float* red) {
#pragma unroll
    for (int o = 16; o > 0; o >>= 1) v += __shfl_xor_sync(0xffffffffu, v, o);
    int wid = threadIdx.x >> 5;
    if ((threadIdx.x & 31) == 0) red[wid] = v;
    __syncthreads();
    float s = 0.f;
#pragma unroll
    for (int w = 0; w < 8; w++) s += red[w];
    __syncthreads();
    return s;
}

// ---------------- fused aggregation + softmax + bias + LN + ELU ------------
// One block (256 threads) per destination node; CSR gather over incoming edges.
// Softmax computed without max subtraction (mathematically identical ratio;
// |e| < ~8 here so exp is safe in fp32).
template <int H>
__global__ void __launch_bounds__(256) agg_kernel(
    const float* __restrict__ hfeat,
    const float* __restrict__ asrc, const float* __restrict__ adst,
    const int* __restrict__ rowptr, const int* __restrict__ colsrc,
    const float* __restrict__ bias, const float* __restrict__ lnw,
    const float* __restrict__ lnb, float* __restrict__ out)
{
    const int C = NF / H;
    int i = blockIdx.x;
    int c = threadIdx.x;
    int head = c / C;

    __shared__ int   sh_src[32];
    __shared__ float sh_ex[32][H];
    __shared__ float sh_ad[H];
    __shared__ float red[8];

    if (c < H) sh_ad[c] = adst[i * H + c];

    // self-loop contribution (PyG add_self_loops=True)
    float e0 = asrc[i * H + head] + adst[i * H + head];
    e0 = e0 > 0.f ? e0 : 0.2f * e0;
    float ex0 = __expf(e0);
    float den = ex0;
    float acc = ex0 * hfeat[(size_t)i * NF + c];

    int beg = rowptr[i], end = rowptr[i + 1];
    for (int p = beg; p < end; p += 32) {
        int cnt = min(32, end - p);
        __syncthreads();  // protect shared reuse from previous chunk
        if (c < cnt) sh_src[c] = colsrc[p + c];
        __syncthreads();
        if (c < cnt * H) {
            int j = c / H, hd = c % H;
            int s2 = sh_src[j];
            float ev = asrc[s2 * H + hd] + sh_ad[hd];
            ev = ev > 0.f ? ev : 0.2f * ev;
            sh_ex[j][hd] = __expf(ev);
        }
        __syncthreads();
#pragma unroll 4
        for (int j = 0; j < cnt; j++) {
            float w = sh_ex[j][head];
            den += w;
            acc += w * hfeat[(size_t)sh_src[j] * NF + c];
        }
    }

    float v = acc / den + bias[c];
    // LayerNorm over 256 channels
    float mean = block_sum256(v, red) * (1.f / NF);
    float dlt = v - mean;
    float var = block_sum256(dlt * dlt, red) * (1.f / NF);
    float y = dlt * rsqrtf(var + 1e-5f) * lnw[c] + lnb[c];
    // ELU
    out[(size_t)i * NF + c] = y > 0.f ? y : expm1f(y);
}

// ---------------- launch ----------------------------------------------------
extern "C" void kernel_launch(void* const* d_in, const int* in_sizes, int n_in,
                              void* d_out, int out_size) {
    const float* x    = (const float*)d_in[0];
    const int*   ei   = (const int*)d_in[1];
    const float* W0   = (const float*)d_in[2];
    const float* as0  = (const float*)d_in[3];
    const float* ad0  = (const float*)d_in[4];
    const float* b0   = (const float*)d_in[5];
    const float* lnw0 = (const float*)d_in[6];
    const float* lnb0 = (const float*)d_in[7];
    const float* W1   = (const float*)d_in[8];
    const float* as1  = (const float*)d_in[9];
    const float* ad1  = (const float*)d_in[10];
    const float* b1   = (const float*)d_in[11];
    const float* lnw1 = (const float*)d_in[12];
    const float* lnb1 = (const float*)d_in[13];
    const float* W2   = (const float*)d_in[14];
    const float* as2  = (const float*)d_in[15];
    const float* ad2  = (const float*)d_in[16];
    const float* b2   = (const float*)d_in[17];
    const float* lnw2 = (const float*)d_in[18];
    const float* lnb2 = (const float*)d_in[19];
    float* out = (float*)d_out;

    int n = in_sizes[0] / 512;   // 50000
    int e = in_sizes[1] / 2;     // 800000
    const int* src = ei;
    const int* dst = ei + e;

    float *ph, *pbuf, *pasrc, *padst;
    int *pcnt, *prow, *pcur, *pcol;
    cudaGetSymbolAddress((void**)&ph, g_h);
    cudaGetSymbolAddress((void**)&pbuf, g_buf);
    cudaGetSymbolAddress((void**)&pasrc, g_asrc);
    cudaGetSymbolAddress((void**)&padst, g_adst);
    cudaGetSymbolAddress((void**)&pcnt, g_cnt);
    cudaGetSymbolAddress((void**)&prow, g_rowptr);
    cudaGetSymbolAddress((void**)&pcur, g_cursor);
    cudaGetSymbolAddress((void**)&pcol, g_colsrc);

    const int TPB = 256;
    // CSR by destination (shared across the three layers)
    zero_cnt_kernel<<<(n + TPB - 1) / TPB, TPB>>>(pcnt, n);
    hist_kernel<<<(e + TPB - 1) / TPB, TPB>>>(dst, pcnt, e);
    scan_kernel<<<1, 1024>>>(pcnt, prow, pcur, n);
    scatter_kernel<<<(e + TPB - 1) / TPB, TPB>>>(src, dst, pcur, pcol, e);

    dim3 ggrid(NF / 128, (n + 127) / 128);

    // layer 0: GATConv(512 -> 4x64)
    gemm_kernel<<<ggrid, 256>>>(x, W0, ph, n, 512);
    alpha_kernel<4><<<n, 256>>>(ph, as0, ad0, pasrc, padst);
    agg_kernel<4><<<n, 256>>>(ph, pasrc, padst, prow, pcol, b0, lnw0, lnb0, pbuf);

    // layer 1: GATConv(256 -> 4x64)
    gemm_kernel<<<ggrid, 256>>>(pbuf, W1, ph, n, 256);
    alpha_kernel<4><<<n, 256>>>(ph, as1, ad1, pasrc, padst);
    agg_kernel<4><<<n, 256>>>(ph, pasrc, padst, prow, pcol, b1, lnw1, lnb1, pbuf);

    // layer 2: GATConv(256 -> 1x256)
    gemm_kernel<<<ggrid, 256>>>(pbuf, W2, ph, n, 256);
    alpha_kernel<1><<<n, 256>>>(ph, as2, ad2, pasrc, padst);
    agg_kernel<1><<<n, 256>>>(ph, pasrc, padst, prow, pcol, b2, lnw2, lnb2, out);
}

// round 3
// speedup vs baseline: 1.2033x; 1.2033x over previous
#include <cuda_runtime.h>
#include <stdint.h>
#include <math.h>

#define MAXN 50000
#define MAXE 800000
#define NF 256

// ---------------- scratch (device globals; no allocation allowed) ----------
__device__ float g_h[(size_t)MAXN * NF];     // GEMM output (pre-aggregation features)
__device__ float g_buf[(size_t)MAXN * NF];   // layer output (post LN+ELU) = next layer input
__device__ float g_asrc[MAXN * 4];
__device__ float g_adst[MAXN * 4];
__device__ int   g_cnt[MAXN];
__device__ int   g_rowptr[MAXN + 1];
__device__ int   g_cursor[MAXN];
__device__ int   g_colsrc[MAXE];

// ---------------- CSR build ------------------------------------------------
__global__ void zero_cnt_kernel(int* __restrict__ cnt, int n) {
    int t = blockIdx.x * blockDim.x + threadIdx.x;
    if (t < n) cnt[t] = 0;
}

__global__ void hist_kernel(const int* __restrict__ dst, int* __restrict__ cnt, int e) {
    int t = blockIdx.x * blockDim.x + threadIdx.x;
    if (t < e) atomicAdd(&cnt[dst[t]], 1);
}

__global__ void scan_kernel(const int* __restrict__ cnt, int* __restrict__ rowptr,
                            int* __restrict__ cursor, int n) {
    __shared__ int sh[1024];
    int tid = threadIdx.x;
    int chunk = (n + 1023) >> 10;
    int base = tid * chunk;
    int s = 0;
    for (int j = 0; j < chunk; j++) {
        int idx = base + j;
        if (idx < n) s += cnt[idx];
    }
    sh[tid] = s;
    __syncthreads();
    for (int off = 1; off < 1024; off <<= 1) {
        int v = (tid >= off) ? sh[tid - off] : 0;
        __syncthreads();
        sh[tid] += v;
        __syncthreads();
    }
    int run = sh[tid] - s;  // exclusive prefix
    for (int j = 0; j < chunk; j++) {
        int idx = base + j;
        if (idx < n) {
            rowptr[idx] = run;
            cursor[idx] = run;
            run += cnt[idx];
        }
    }
    if (tid == 1023) rowptr[n] = run;
}

__global__ void scatter_kernel(const int* __restrict__ src, const int* __restrict__ dst,
                               int* __restrict__ cursor, int* __restrict__ colsrc, int e) {
    int t = blockIdx.x * blockDim.x + threadIdx.x;
    if (t < e) {
        int d = dst[t];
        int p = atomicAdd(&cursor[d], 1);
        colsrc[p] = src[t];
    }
}

// ---------------- tf32 helpers ----------------------------------------------
__device__ __forceinline__ float tf32_rna(float x) {
    uint32_t u;
    asm("cvt.rna.tf32.f32 %0, %1;" : "=r"(u) : "f"(x));
    return __uint_as_float(u);
}

__device__ __forceinline__ void mma_tf32(float c[4],
                                         uint32_t a0, uint32_t a1, uint32_t a2, uint32_t a3,
                                         uint32_t b0, uint32_t b1) {
    asm volatile(
        "mma.sync.aligned.m16n8k8.row.col.f32.tf32.tf32.f32 "
        "{%0,%1,%2,%3}, {%4,%5,%6,%7}, {%8,%9}, {%0,%1,%2,%3};"
        : "+f"(c[0]), "+f"(c[1]), "+f"(c[2]), "+f"(c[3])
        : "r"(a0), "r"(a1), "r"(a2), "r"(a3), "r"(b0), "r"(b1));
}

// ---------------- tensor-core GEMM: C[M,256] = A[M,K] @ B[K,256] ------------
// 128x128 CTA tile, BK=16, 8 warps (2x4), warp tile 64x32, m16n8k8 tf32 mma
// with 3xTF32 split (hi*hi + hi*lo + lo*hi) for near-fp32 accuracy.
// Shared layouts: A [row][k] stride 20 floats, B [k][n] stride 136 floats
// (both conflict-free for the mma fragment access pattern, float4-aligned).
__global__ void __launch_bounds__(256, 2) gemm_tc(
    const float* __restrict__ A, const float* __restrict__ B,
    float* __restrict__ C, int M, int K)
{
    __shared__ float4 As_hi4[128 * 5];   // 128 rows x 20 floats
    __shared__ float4 As_lo4[128 * 5];
    __shared__ float4 Bs_hi4[16 * 34];   // 16 k-rows x 136 floats
    __shared__ float4 Bs_lo4[16 * 34];
    const float* As_hi = (const float*)As_hi4;
    const float* As_lo = (const float*)As_lo4;
    const float* Bs_hi = (const float*)Bs_hi4;
    const float* Bs_lo = (const float*)Bs_lo4;

    const int tid  = threadIdx.x;
    const int lane = tid & 31;
    const int w    = tid >> 5;
    const int g    = lane >> 2;      // group (row within fragment)
    const int t    = lane & 3;       // thread in group (k within fragment)
    const int wm   = w >> 2;         // 0..1
    const int wn   = w & 3;          // 0..3

    const int row0 = blockIdx.y * 128;
    const int col0 = blockIdx.x * 128;

    // staging indices (2 float4 jobs per thread for each of A, B)
    const int ar0 = tid >> 2;            // A rows 0..63
    const int ar1 = 64 + (tid >> 2);     // A rows 64..127
    const int ac4 = tid & 3;             // A float4-col 0..3
    const int bk0 = tid >> 5;            // B k 0..7
    const int bk1 = 8 + (tid >> 5);      // B k 8..15
    const int bc4 = tid & 31;            // B float4-col 0..31

    const bool ok0 = (row0 + ar0) < M;
    const bool ok1 = (row0 + ar1) < M;

    float acc[4][4][4];
#pragma unroll
    for (int mt = 0; mt < 4; mt++)
#pragma unroll
        for (int nt = 0; nt < 4; nt++)
#pragma unroll
            for (int i = 0; i < 4; i++) acc[mt][nt][i] = 0.f;

    const float4 z4 = make_float4(0.f, 0.f, 0.f, 0.f);
    float4 pa0, pa1, pb0, pb1;

    // prefetch tile 0
    pa0 = ok0 ? *(const float4*)(A + (size_t)(row0 + ar0) * K + ac4 * 4) : z4;
    pa1 = ok1 ? *(const float4*)(A + (size_t)(row0 + ar1) * K + ac4 * 4) : z4;
    pb0 = *(const float4*)(B + (size_t)bk0 * NF + col0 + bc4 * 4);
    pb1 = *(const float4*)(B + (size_t)bk1 * NF + col0 + bc4 * 4);

    for (int kt = 0; kt < K; kt += 16) {
        // convert + store staged tile to shared
        {
            float4 h, l;
            h.x = tf32_rna(pa0.x); l.x = tf32_rna(pa0.x - h.x);
            h.y = tf32_rna(pa0.y); l.y = tf32_rna(pa0.y - h.y);
            h.z = tf32_rna(pa0.z); l.z = tf32_rna(pa0.z - h.z);
            h.w = tf32_rna(pa0.w); l.w = tf32_rna(pa0.w - h.w);
            As_hi4[ar0 * 5 + ac4] = h; As_lo4[ar0 * 5 + ac4] = l;
            h.x = tf32_rna(pa1.x); l.x = tf32_rna(pa1.x - h.x);
            h.y = tf32_rna(pa1.y); l.y = tf32_rna(pa1.y - h.y);
            h.z = tf32_rna(pa1.z); l.z = tf32_rna(pa1.z - h.z);
            h.w = tf32_rna(pa1.w); l.w = tf32_rna(pa1.w - h.w);
            As_hi4[ar1 * 5 + ac4] = h; As_lo4[ar1 * 5 + ac4] = l;
            h.x = tf32_rna(pb0.x); l.x = tf32_rna(pb0.x - h.x);
            h.y = tf32_rna(pb0.y); l.y = tf32_rna(pb0.y - h.y);
            h.z = tf32_rna(pb0.z); l.z = tf32_rna(pb0.z - h.z);
            h.w = tf32_rna(pb0.w); l.w = tf32_rna(pb0.w - h.w);
            Bs_hi4[bk0 * 34 + bc4] = h; Bs_lo4[bk0 * 34 + bc4] = l;
            h.x = tf32_rna(pb1.x); l.x = tf32_rna(pb1.x - h.x);
            h.y = tf32_rna(pb1.y); l.y = tf32_rna(pb1.y - h.y);
            h.z = tf32_rna(pb1.z); l.z = tf32_rna(pb1.z - h.z);
            h.w = tf32_rna(pb1.w); l.w = tf32_rna(pb1.w - h.w);
            Bs_hi4[bk1 * 34 + bc4] = h; Bs_lo4[bk1 * 34 + bc4] = l;
        }
        __syncthreads();

        // prefetch next tile (overlaps with mma work below)
        int ktn = kt + 16;
        if (ktn < K) {
            pa0 = ok0 ? *(const float4*)(A + (size_t)(row0 + ar0) * K + ktn + ac4 * 4) : z4;
            pa1 = ok1 ? *(const float4*)(A + (size_t)(row0 + ar1) * K + ktn + ac4 * 4) : z4;
            pb0 = *(const float4*)(B + (size_t)(ktn + bk0) * NF + col0 + bc4 * 4);
            pb1 = *(const float4*)(B + (size_t)(ktn + bk1) * NF + col0 + bc4 * 4);
        }

#pragma unroll
        for (int kk = 0; kk < 16; kk += 8) {
            uint32_t bh[4][2], bl[4][2];
            const int cb = wn * 32;
#pragma unroll
            for (int nt = 0; nt < 4; nt++) {
                int col = cb + nt * 8 + g;
                bh[nt][0] = __float_as_uint(Bs_hi[(kk + t) * 136 + col]);
                bh[nt][1] = __float_as_uint(Bs_hi[(kk + t + 4) * 136 + col]);
                bl[nt][0] = __float_as_uint(Bs_lo[(kk + t) * 136 + col]);
                bl[nt][1] = __float_as_uint(Bs_lo[(kk + t + 4) * 136 + col]);
            }
#pragma unroll
            for (int mt = 0; mt < 4; mt++) {
                int rb = wm * 64 + mt * 16 + g;
                uint32_t ah[4], al[4];
                ah[0] = __float_as_uint(As_hi[rb * 20 + kk + t]);
                ah[1] = __float_as_uint(As_hi[(rb + 8) * 20 + kk + t]);
                ah[2] = __float_as_uint(As_hi[rb * 20 + kk + t + 4]);
                ah[3] = __float_as_uint(As_hi[(rb + 8) * 20 + kk + t + 4]);
                al[0] = __float_as_uint(As_lo[rb * 20 + kk + t]);
                al[1] = __float_as_uint(As_lo[(rb + 8) * 20 + kk + t]);
                al[2] = __float_as_uint(As_lo[rb * 20 + kk + t + 4]);
                al[3] = __float_as_uint(As_lo[(rb + 8) * 20 + kk + t + 4]);
#pragma unroll
                for (int nt = 0; nt < 4; nt++) {
                    mma_tf32(acc[mt][nt], ah[0], ah[1], ah[2], ah[3], bh[nt][0], bh[nt][1]);
                    mma_tf32(acc[mt][nt], ah[0], ah[1], ah[2], ah[3], bl[nt][0], bl[nt][1]);
                    mma_tf32(acc[mt][nt], al[0], al[1], al[2], al[3], bh[nt][0], bh[nt][1]);
                }
            }
        }
        __syncthreads();
    }

    // epilogue: each fragment row pair -> float2 stores
#pragma unroll
    for (int mt = 0; mt < 4; mt++) {
        int r0 = row0 + wm * 64 + mt * 16 + g;
        int r1 = r0 + 8;
#pragma unroll
        for (int nt = 0; nt < 4; nt++) {
            int col = col0 + wn * 32 + nt * 8 + 2 * t;
            if (r0 < M)
                *(float2*)(C + (size_t)r0 * NF + col) = make_float2(acc[mt][nt][0], acc[mt][nt][1]);
            if (r1 < M)
                *(float2*)(C + (size_t)r1 * NF + col) = make_float2(acc[mt][nt][2], acc[mt][nt][3]);
        }
    }
}

// ---------------- alpha projections: asrc/adst[i,h] = sum_c h[i,h,c]*a[h,c] -
template <int H>
__global__ void __launch_bounds__(256) alpha_kernel(
    const float* __restrict__ hfeat,
    const float* __restrict__ a_s, const float* __restrict__ a_d,
    float* __restrict__ asrc, float* __restrict__ adst)
{
    const int C = NF / H;
    int i = blockIdx.x;
    int c = threadIdx.x;
    float hv = hfeat[(size_t)i * NF + c];
    float ps = hv * a_s[c];
    float pd = hv * a_d[c];
#pragma unroll
    for (int o = 16; o > 0; o >>= 1) {
        ps += __shfl_xor_sync(0xffffffffu, ps, o);
        pd += __shfl_xor_sync(0xffffffffu, pd, o);
    }
    __shared__ float ss[8], sd[8];
    int wid = c >> 5;
    if ((c & 31) == 0) { ss[wid] = ps; sd[wid] = pd; }
    __syncthreads();
    if (c < H) {
        const int wph = C >> 5;  // warps per head
        float rs = 0.f, rd = 0.f;
#pragma unroll
        for (int w = 0; w < wph; w++) { rs += ss[c * wph + w]; rd += sd[c * wph + w]; }
        asrc[i * H + c] = rs;
        adst[i * H + c] = rd;
    }
}

// ---------------- block-sum helper -----------------------------------------
__device__ __forceinline__ float block_sum256(float v, float* red) {
#pragma unroll
    for (int o = 16; o > 0; o >>= 1) v += __shfl_xor_sync(0xffffffffu, v, o);
    int wid = threadIdx.x >> 5;
    if ((threadIdx.x & 31) == 0) red[wid] = v;
    __syncthreads();
    float s = 0.f;
#pragma unroll
    for (int w = 0; w < 8; w++) s += red[w];
    __syncthreads();
    return s;
}

// ---------------- fused aggregation + softmax + bias + LN + ELU ------------
template <int H>
__global__ void __launch_bounds__(256) agg_kernel(
    const float* __restrict__ hfeat,
    const float* __restrict__ asrc, const float* __restrict__ adst,
    const int* __restrict__ rowptr, const int* __restrict__ colsrc,
    const float* __restrict__ bias, const float* __restrict__ lnw,
    const float* __restrict__ lnb, float* __restrict__ out)
{
    const int C = NF / H;
    int i = blockIdx.x;
    int c = threadIdx.x;
    int head = c / C;

    __shared__ int   sh_src[32];
    __shared__ float sh_ex[32][H];
    __shared__ float sh_ad[H];
    __shared__ float red[8];

    if (c < H) sh_ad[c] = adst[i * H + c];

    // self-loop contribution (PyG add_self_loops=True)
    float e0 = asrc[i * H + head] + adst[i * H + head];
    e0 = e0 > 0.f ? e0 : 0.2f * e0;
    float ex0 = __expf(e0);
    float den = ex0;
    float acc = ex0 * hfeat[(size_t)i * NF + c];

    int beg = rowptr[i], end = rowptr[i + 1];
    for (int p = beg; p < end; p += 32) {
        int cnt = min(32, end - p);
        __syncthreads();  // protect shared reuse from previous chunk
        if (c < cnt) sh_src[c] = colsrc[p + c];
        __syncthreads();
        if (c < cnt * H) {
            int j = c / H, hd = c % H;
            int s2 = sh_src[j];
            float ev = asrc[s2 * H + hd] + sh_ad[hd];
            ev = ev > 0.f ? ev : 0.2f * ev;
            sh_ex[j][hd] = __expf(ev);
        }
        __syncthreads();
#pragma unroll 4
        for (int j = 0; j < cnt; j++) {
            float w = sh_ex[j][head];
            den += w;
            acc += w * hfeat[(size_t)sh_src[j] * NF + c];
        }
    }

    float v = acc / den + bias[c];
    // LayerNorm over 256 channels
    float mean = block_sum256(v, red) * (1.f / NF);
    float dlt = v - mean;
    float var = block_sum256(dlt * dlt, red) * (1.f / NF);
    float y = dlt * rsqrtf(var + 1e-5f) * lnw[c] + lnb[c];
    // ELU
    out[(size_t)i * NF + c] = y > 0.f ? y : expm1f(y);
}

// ---------------- launch ----------------------------------------------------
extern "C" void kernel_launch(void* const* d_in, const int* in_sizes, int n_in,
                              void* d_out, int out_size) {
    const float* x    = (const float*)d_in[0];
    const int*   ei   = (const int*)d_in[1];
    const float* W0   = (const float*)d_in[2];
    const float* as0  = (const float*)d_in[3];
    const float* ad0  = (const float*)d_in[4];
    const float* b0   = (const float*)d_in[5];
    const float* lnw0 = (const float*)d_in[6];
    const float* lnb0 = (const float*)d_in[7];
    const float* W1   = (const float*)d_in[8];
    const float* as1  = (const float*)d_in[9];
    const float* ad1  = (const float*)d_in[10];
    const float* b1   = (const float*)d_in[11];
    const float* lnw1 = (const float*)d_in[12];
    const float* lnb1 = (const float*)d_in[13];
    const float* W2   = (const float*)d_in[14];
    const float* as2  = (const float*)d_in[15];
    const float* ad2  = (const float*)d_in[16];
    const float* b2   = (const float*)d_in[17];
    const float* lnw2 = (const float*)d_in[18];
    const float* lnb2 = (const float*)d_in[19];
    float* out = (float*)d_out;

    int n = in_sizes[0] / 512;   // 50000
    int e = in_sizes[1] / 2;     // 800000
    const int* src = ei;
    const int* dst = ei + e;

    float *ph, *pbuf, *pasrc, *padst;
    int *pcnt, *prow, *pcur, *pcol;
    cudaGetSymbolAddress((void**)&ph, g_h);
    cudaGetSymbolAddress((void**)&pbuf, g_buf);
    cudaGetSymbolAddress((void**)&pasrc, g_asrc);
    cudaGetSymbolAddress((void**)&padst, g_adst);
    cudaGetSymbolAddress((void**)&pcnt, g_cnt);
    cudaGetSymbolAddress((void**)&prow, g_rowptr);
    cudaGetSymbolAddress((void**)&pcur, g_cursor);
    cudaGetSymbolAddress((void**)&pcol, g_colsrc);

    const int TPB = 256;
    // CSR by destination (shared across the three layers)
    zero_cnt_kernel<<<(n + TPB - 1) / TPB, TPB>>>(pcnt, n);
    hist_kernel<<<(e + TPB - 1) / TPB, TPB>>>(dst, pcnt, e);
    scan_kernel<<<1, 1024>>>(pcnt, prow, pcur, n);
    scatter_kernel<<<(e + TPB - 1) / TPB, TPB>>>(src, dst, pcur, pcol, e);

    dim3 ggrid(NF / 128, (n + 127) / 128);

    // layer 0: GATConv(512 -> 4x64)
    gemm_tc<<<ggrid, 256>>>(x, W0, ph, n, 512);
    alpha_kernel<4><<<n, 256>>>(ph, as0, ad0, pasrc, padst);
    agg_kernel<4><<<n, 256>>>(ph, pasrc, padst, prow, pcol, b0, lnw0, lnb0, pbuf);

    // layer 1: GATConv(256 -> 4x64)
    gemm_tc<<<ggrid, 256>>>(pbuf, W1, ph, n, 256);
    alpha_kernel<4><<<n, 256>>>(ph, as1, ad1, pasrc, padst);
    agg_kernel<4><<<n, 256>>>(ph, pasrc, padst, prow, pcol, b1, lnw1, lnb1, pbuf);

    // layer 2: GATConv(256 -> 1x256)
    gemm_tc<<<ggrid, 256>>>(pbuf, W2, ph, n, 256);
    alpha_kernel<1><<<n, 256>>>(ph, as2, ad2, pasrc, padst);
    agg_kernel<1><<<n, 256>>>(ph, pasrc, padst, prow, pcol, b2, lnw2, lnb2, out);
}

// round 4
// speedup vs baseline: 1.2751x; 1.0597x over previous
#include <cuda_runtime.h>
#include <stdint.h>
#include <math.h>

#define MAXN 50000
#define MAXE 800000
#define NF 256

// ---------------- scratch (device globals; no allocation allowed) ----------
__device__ float g_h[(size_t)MAXN * NF];     // GEMM output (pre-aggregation features)
__device__ float g_buf[(size_t)MAXN * NF];   // layer output (post LN+ELU) = next layer input
// per-layer alpha buffers: [layer][asrc|adst][MAXN*4]
__device__ float g_alpha[(size_t)6 * MAXN * 4];
__device__ int   g_cnt[MAXN];                // zero-initialized; scan re-zeroes for next call
__device__ int   g_rowptr[MAXN + 1];
__device__ int   g_cursor[MAXN];
__device__ int   g_colsrc[MAXE];

// ---------------- CSR build ------------------------------------------------
// hist also zeroes the alpha accumulation buffers (needed before each gemm).
__global__ void hist_kernel(const int* __restrict__ dst, int* __restrict__ cnt,
                            float* __restrict__ alpha, int e) {
    int t = blockIdx.x * blockDim.x + threadIdx.x;
    if (t < e) atomicAdd(&cnt[dst[t]], 1);
    const int total = 6 * MAXN * 4;
    for (int i = t; i < total; i += gridDim.x * blockDim.x) alpha[i] = 0.f;
}

__global__ void scan_kernel(int* __restrict__ cnt, int* __restrict__ rowptr,
                            int* __restrict__ cursor, int n) {
    __shared__ int sh[1024];
    int tid = threadIdx.x;
    int chunk = (n + 1023) >> 10;
    int base = tid * chunk;
    int s = 0;
    for (int j = 0; j < chunk; j++) {
        int idx = base + j;
        if (idx < n) s += cnt[idx];
    }
    sh[tid] = s;
    __syncthreads();
    for (int off = 1; off < 1024; off <<= 1) {
        int v = (tid >= off) ? sh[tid - off] : 0;
        __syncthreads();
        sh[tid] += v;
        __syncthreads();
    }
    int run = sh[tid] - s;  // exclusive prefix
    for (int j = 0; j < chunk; j++) {
        int idx = base + j;
        if (idx < n) {
            rowptr[idx] = run;
            cursor[idx] = run;
            run += cnt[idx];
            cnt[idx] = 0;   // re-zero for the next kernel_launch call (graph replay)
        }
    }
    if (tid == 1023) rowptr[n] = run;
}

__global__ void scatter_kernel(const int* __restrict__ src, const int* __restrict__ dst,
                               int* __restrict__ cursor, int* __restrict__ colsrc, int e) {
    int t = blockIdx.x * blockDim.x + threadIdx.x;
    if (t < e) {
        int d = dst[t];
        int p = atomicAdd(&cursor[d], 1);
        colsrc[p] = src[t];
    }
}

// ---------------- tf32 helpers ----------------------------------------------
__device__ __forceinline__ float tf32_rna(float x) {
    uint32_t u;
    asm("cvt.rna.tf32.f32 %0, %1;" : "=r"(u) : "f"(x));
    return __uint_as_float(u);
}

__device__ __forceinline__ void mma_tf32(float c[4],
                                         uint32_t a0, uint32_t a1, uint32_t a2, uint32_t a3,
                                         uint32_t b0, uint32_t b1) {
    asm volatile(
        "mma.sync.aligned.m16n8k8.row.col.f32.tf32.tf32.f32 "
        "{%0,%1,%2,%3}, {%4,%5,%6,%7}, {%8,%9}, {%0,%1,%2,%3};"
        : "+f"(c[0]), "+f"(c[1]), "+f"(c[2]), "+f"(c[3])
        : "r"(a0), "r"(a1), "r"(a2), "r"(a3), "r"(b0), "r"(b1));
}

// ---------------- tensor-core GEMM + fused alpha projection -----------------
// C[M,256] = A[M,K] @ B[K,256]; also accumulates (atomically)
//   asrc[i,h] += sum_c C[i,c]*a_s[c],  adst[i,h] += sum_c C[i,c]*a_d[c]
// 128x128 CTA tile, BK=16, 8 warps (2x4), warp tile 64x32, m16n8k8 tf32 mma
// with 3xTF32 split (hi*hi + hi*lo + lo*hi) for near-fp32 accuracy.
template <int H>
__global__ void __launch_bounds__(256, 2) gemm_tc(
    const float* __restrict__ A, const float* __restrict__ B,
    float* __restrict__ C, int M, int K,
    const float* __restrict__ a_s, const float* __restrict__ a_d,
    float* __restrict__ asrc, float* __restrict__ adst)
{
    __shared__ float4 As_hi4[128 * 5];   // 128 rows x 20 floats
    __shared__ float4 As_lo4[128 * 5];
    __shared__ float4 Bs_hi4[16 * 34];   // 16 k-rows x 136 floats
    __shared__ float4 Bs_lo4[16 * 34];
    const float* As_hi = (const float*)As_hi4;
    const float* As_lo = (const float*)As_lo4;
    const float* Bs_hi = (const float*)Bs_hi4;
    const float* Bs_lo = (const float*)Bs_lo4;

    const int tid  = threadIdx.x;
    const int lane = tid & 31;
    const int w    = tid >> 5;
    const int g    = lane >> 2;      // group (row within fragment)
    const int t    = lane & 3;       // thread in group (k within fragment)
    const int wm   = w >> 2;         // 0..1
    const int wn   = w & 3;          // 0..3

    const int row0 = blockIdx.y * 128;
    const int col0 = blockIdx.x * 128;

    const int ar0 = tid >> 2;            // A rows 0..63
    const int ar1 = 64 + (tid >> 2);     // A rows 64..127
    const int ac4 = tid & 3;             // A float4-col 0..3
    const int bk0 = tid >> 5;            // B k 0..7
    const int bk1 = 8 + (tid >> 5);      // B k 8..15
    const int bc4 = tid & 31;            // B float4-col 0..31

    const bool ok0 = (row0 + ar0) < M;
    const bool ok1 = (row0 + ar1) < M;

    float acc[4][4][4];
#pragma unroll
    for (int mt = 0; mt < 4; mt++)
#pragma unroll
        for (int nt = 0; nt < 4; nt++)
#pragma unroll
            for (int i = 0; i < 4; i++) acc[mt][nt][i] = 0.f;

    const float4 z4 = make_float4(0.f, 0.f, 0.f, 0.f);
    float4 pa0, pa1, pb0, pb1;

    pa0 = ok0 ? *(const float4*)(A + (size_t)(row0 + ar0) * K + ac4 * 4) : z4;
    pa1 = ok1 ? *(const float4*)(A + (size_t)(row0 + ar1) * K + ac4 * 4) : z4;
    pb0 = *(const float4*)(B + (size_t)bk0 * NF + col0 + bc4 * 4);
    pb1 = *(const float4*)(B + (size_t)bk1 * NF + col0 + bc4 * 4);

    for (int kt = 0; kt < K; kt += 16) {
        {
            float4 h, l;
            h.x = tf32_rna(pa0.x); l.x = tf32_rna(pa0.x - h.x);
            h.y = tf32_rna(pa0.y); l.y = tf32_rna(pa0.y - h.y);
            h.z = tf32_rna(pa0.z); l.z = tf32_rna(pa0.z - h.z);
            h.w = tf32_rna(pa0.w); l.w = tf32_rna(pa0.w - h.w);
            As_hi4[ar0 * 5 + ac4] = h; As_lo4[ar0 * 5 + ac4] = l;
            h.x = tf32_rna(pa1.x); l.x = tf32_rna(pa1.x - h.x);
            h.y = tf32_rna(pa1.y); l.y = tf32_rna(pa1.y - h.y);
            h.z = tf32_rna(pa1.z); l.z = tf32_rna(pa1.z - h.z);
            h.w = tf32_rna(pa1.w); l.w = tf32_rna(pa1.w - h.w);
            As_hi4[ar1 * 5 + ac4] = h; As_lo4[ar1 * 5 + ac4] = l;
            h.x = tf32_rna(pb0.x); l.x = tf32_rna(pb0.x - h.x);
            h.y = tf32_rna(pb0.y); l.y = tf32_rna(pb0.y - h.y);
            h.z = tf32_rna(pb0.z); l.z = tf32_rna(pb0.z - h.z);
            h.w = tf32_rna(pb0.w); l.w = tf32_rna(pb0.w - h.w);
            Bs_hi4[bk0 * 34 + bc4] = h; Bs_lo4[bk0 * 34 + bc4] = l;
            h.x = tf32_rna(pb1.x); l.x = tf32_rna(pb1.x - h.x);
            h.y = tf32_rna(pb1.y); l.y = tf32_rna(pb1.y - h.y);
            h.z = tf32_rna(pb1.z); l.z = tf32_rna(pb1.z - h.z);
            h.w = tf32_rna(pb1.w); l.w = tf32_rna(pb1.w - h.w);
            Bs_hi4[bk1 * 34 + bc4] = h; Bs_lo4[bk1 * 34 + bc4] = l;
        }
        __syncthreads();

        int ktn = kt + 16;
        if (ktn < K) {
            pa0 = ok0 ? *(const float4*)(A + (size_t)(row0 + ar0) * K + ktn + ac4 * 4) : z4;
            pa1 = ok1 ? *(const float4*)(A + (size_t)(row0 + ar1) * K + ktn + ac4 * 4) : z4;
            pb0 = *(const float4*)(B + (size_t)(ktn + bk0) * NF + col0 + bc4 * 4);
            pb1 = *(const float4*)(B + (size_t)(ktn + bk1) * NF + col0 + bc4 * 4);
        }

#pragma unroll
        for (int kk = 0; kk < 16; kk += 8) {
            uint32_t bh[4][2], bl[4][2];
            const int cb = wn * 32;
#pragma unroll
            for (int nt = 0; nt < 4; nt++) {
                int col = cb + nt * 8 + g;
                bh[nt][0] = __float_as_uint(Bs_hi[(kk + t) * 136 + col]);
                bh[nt][1] = __float_as_uint(Bs_hi[(kk + t + 4) * 136 + col]);
                bl[nt][0] = __float_as_uint(Bs_lo[(kk + t) * 136 + col]);
                bl[nt][1] = __float_as_uint(Bs_lo[(kk + t + 4) * 136 + col]);
            }
#pragma unroll
            for (int mt = 0; mt < 4; mt++) {
                int rb = wm * 64 + mt * 16 + g;
                uint32_t ah[4], al[4];
                ah[0] = __float_as_uint(As_hi[rb * 20 + kk + t]);
                ah[1] = __float_as_uint(As_hi[(rb + 8) * 20 + kk + t]);
                ah[2] = __float_as_uint(As_hi[rb * 20 + kk + t + 4]);
                ah[3] = __float_as_uint(As_hi[(rb + 8) * 20 + kk + t + 4]);
                al[0] = __float_as_uint(As_lo[rb * 20 + kk + t]);
                al[1] = __float_as_uint(As_lo[(rb + 8) * 20 + kk + t]);
                al[2] = __float_as_uint(As_lo[rb * 20 + kk + t + 4]);
                al[3] = __float_as_uint(As_lo[(rb + 8) * 20 + kk + t + 4]);
#pragma unroll
                for (int nt = 0; nt < 4; nt++) {
                    mma_tf32(acc[mt][nt], ah[0], ah[1], ah[2], ah[3], bh[nt][0], bh[nt][1]);
                    mma_tf32(acc[mt][nt], ah[0], ah[1], ah[2], ah[3], bl[nt][0], bl[nt][1]);
                    mma_tf32(acc[mt][nt], al[0], al[1], al[2], al[3], bh[nt][0], bh[nt][1]);
                }
            }
        }
        __syncthreads();
    }

    // ---- epilogue 1: store C tile ----
#pragma unroll
    for (int mt = 0; mt < 4; mt++) {
        int r0 = row0 + wm * 64 + mt * 16 + g;
        int r1 = r0 + 8;
#pragma unroll
        for (int nt = 0; nt < 4; nt++) {
            int col = col0 + wn * 32 + nt * 8 + 2 * t;
            if (r0 < M)
                *(float2*)(C + (size_t)r0 * NF + col) = make_float2(acc[mt][nt][0], acc[mt][nt][1]);
            if (r1 < M)
                *(float2*)(C + (size_t)r1 * NF + col) = make_float2(acc[mt][nt][2], acc[mt][nt][3]);
        }
    }

    // ---- epilogue 2: fused alpha projection ----
    // Each thread's 8 cols lie in one head (32-col warp stripe, head size >= 64).
    {
        float asv[4][2], adv[4][2];
#pragma unroll
        for (int nt = 0; nt < 4; nt++)
#pragma unroll
            for (int i = 0; i < 2; i++) {
                int gcol = col0 + wn * 32 + nt * 8 + 2 * t + i;
                asv[nt][i] = a_s[gcol];
                adv[nt][i] = a_d[gcol];
            }
        const int hd = (H == 4) ? ((col0 + wn * 32) >> 6) : 0;
#pragma unroll
        for (int mt = 0; mt < 4; mt++) {
            float sa0 = 0.f, sd0 = 0.f, sa1 = 0.f, sd1 = 0.f;
#pragma unroll
            for (int nt = 0; nt < 4; nt++)
#pragma unroll
                for (int i = 0; i < 2; i++) {
                    sa0 += acc[mt][nt][i]     * asv[nt][i];
                    sd0 += acc[mt][nt][i]     * adv[nt][i];
                    sa1 += acc[mt][nt][2 + i] * asv[nt][i];
                    sd1 += acc[mt][nt][2 + i] * adv[nt][i];
                }
#pragma unroll
            for (int o = 1; o <= 2; o <<= 1) {
                sa0 += __shfl_xor_sync(0xffffffffu, sa0, o);
                sd0 += __shfl_xor_sync(0xffffffffu, sd0, o);
                sa1 += __shfl_xor_sync(0xffffffffu, sa1, o);
                sd1 += __shfl_xor_sync(0xffffffffu, sd1, o);
            }
            if (t == 0) {
                int r0 = row0 + wm * 64 + mt * 16 + g;
                int r1 = r0 + 8;
                if (r0 < M) {
                    atomicAdd(&asrc[r0 * H + hd], sa0);
                    atomicAdd(&adst[r0 * H + hd], sd0);
                }
                if (r1 < M) {
                    atomicAdd(&asrc[r1 * H + hd], sa1);
                    atomicAdd(&adst[r1 * H + hd], sd1);
                }
            }
        }
    }
}

// ---------------- block-sum helper -----------------------------------------
__device__ __forceinline__ float block_sum256(float v, float* red) {
#pragma unroll
    for (int o = 16; o > 0; o >>= 1) v += __shfl_xor_sync(0xffffffffu, v, o);
    int wid = threadIdx.x >> 5;
    if ((threadIdx.x & 31) == 0) red[wid] = v;
    __syncthreads();
    float s = 0.f;
#pragma unroll
    for (int w = 0; w < 8; w++) s += red[w];
    __syncthreads();
    return s;
}

// ---------------- fused aggregation + softmax + bias + LN + ELU ------------
template <int H>
__global__ void __launch_bounds__(256) agg_kernel(
    const float* __restrict__ hfeat,
    const float* __restrict__ asrc, const float* __restrict__ adst,
    const int* __restrict__ rowptr, const int* __restrict__ colsrc,
    const float* __restrict__ bias, const float* __restrict__ lnw,
    const float* __restrict__ lnb, float* __restrict__ out)
{
    const int C = NF / H;
    int i = blockIdx.x;
    int c = threadIdx.x;
    int head = c / C;

    __shared__ int   sh_src[32];
    __shared__ float sh_ex[32][H];
    __shared__ float sh_ad[H];
    __shared__ float red[8];

    if (c < H) sh_ad[c] = adst[i * H + c];

    // self-loop contribution (PyG add_self_loops=True)
    float e0 = asrc[i * H + head] + adst[i * H + head];
    e0 = e0 > 0.f ? e0 : 0.2f * e0;
    float ex0 = __expf(e0);
    float den = ex0;
    float acc = ex0 * hfeat[(size_t)i * NF + c];

    int beg = rowptr[i], end = rowptr[i + 1];
    for (int p = beg; p < end; p += 32) {
        int cnt = min(32, end - p);
        __syncthreads();  // protect shared reuse from previous chunk
        if (c < cnt) sh_src[c] = colsrc[p + c];
        __syncthreads();
        if (c < cnt * H) {
            int j = c / H, hd = c % H;
            int s2 = sh_src[j];
            float ev = asrc[s2 * H + hd] + sh_ad[hd];
            ev = ev > 0.f ? ev : 0.2f * ev;
            sh_ex[j][hd] = __expf(ev);
        }
        __syncthreads();
#pragma unroll 8
        for (int j = 0; j < cnt; j++) {
            float w = sh_ex[j][head];
            den += w;
            acc += w * hfeat[(size_t)sh_src[j] * NF + c];
        }
    }

    float v = acc / den + bias[c];
    float mean = block_sum256(v, red) * (1.f / NF);
    float dlt = v - mean;
    float var = block_sum256(dlt * dlt, red) * (1.f / NF);
    float y = dlt * rsqrtf(var + 1e-5f) * lnw[c] + lnb[c];
    out[(size_t)i * NF + c] = y > 0.f ? y : expm1f(y);
}

// ---------------- launch ----------------------------------------------------
extern "C" void kernel_launch(void* const* d_in, const int* in_sizes, int n_in,
                              void* d_out, int out_size) {
    const float* x    = (const float*)d_in[0];
    const int*   ei   = (const int*)d_in[1];
    const float* W0   = (const float*)d_in[2];
    const float* as0  = (const float*)d_in[3];
    const float* ad0  = (const float*)d_in[4];
    const float* b0   = (const float*)d_in[5];
    const float* lnw0 = (const float*)d_in[6];
    const float* lnb0 = (const float*)d_in[7];
    const float* W1   = (const float*)d_in[8];
    const float* as1  = (const float*)d_in[9];
    const float* ad1  = (const float*)d_in[10];
    const float* b1   = (const float*)d_in[11];
    const float* lnw1 = (const float*)d_in[12];
    const float* lnb1 = (const float*)d_in[13];
    const float* W2   = (const float*)d_in[14];
    const float* as2  = (const float*)d_in[15];
    const float* ad2  = (const float*)d_in[16];
    const float* b2   = (const float*)d_in[17];
    const float* lnw2 = (const float*)d_in[18];
    const float* lnb2 = (const float*)d_in[19];
    float* out = (float*)d_out;

    int n = in_sizes[0] / 512;   // 50000
    int e = in_sizes[1] / 2;     // 800000
    const int* src = ei;
    const int* dst = ei + e;

    float *ph, *pbuf, *palpha;
    int *pcnt, *prow, *pcur, *pcol;
    cudaGetSymbolAddress((void**)&ph, g_h);
    cudaGetSymbolAddress((void**)&pbuf, g_buf);
    cudaGetSymbolAddress((void**)&palpha, g_alpha);
    cudaGetSymbolAddress((void**)&pcnt, g_cnt);
    cudaGetSymbolAddress((void**)&prow, g_rowptr);
    cudaGetSymbolAddress((void**)&pcur, g_cursor);
    cudaGetSymbolAddress((void**)&pcol, g_colsrc);

    // per-layer alpha buffers
    float* pas0 = palpha + (size_t)0 * MAXN * 4;
    float* pad0 = palpha + (size_t)1 * MAXN * 4;
    float* pas1 = palpha + (size_t)2 * MAXN * 4;
    float* pad1 = palpha + (size_t)3 * MAXN * 4;
    float* pas2 = palpha + (size_t)4 * MAXN * 4;
    float* pad2 = palpha + (size_t)5 * MAXN * 4;

    const int TPB = 256;
    // CSR by destination (shared across the three layers); hist zeroes alpha bufs
    hist_kernel<<<(e + TPB - 1) / TPB, TPB>>>(dst, pcnt, palpha, e);
    scan_kernel<<<1, 1024>>>(pcnt, prow, pcur, n);
    scatter_kernel<<<(e + TPB - 1) / TPB, TPB>>>(src, dst, pcur, pcol, e);

    dim3 ggrid(NF / 128, (n + 127) / 128);

    // layer 0: GATConv(512 -> 4x64)
    gemm_tc<4><<<ggrid, 256>>>(x, W0, ph, n, 512, as0, ad0, pas0, pad0);
    agg_kernel<4><<<n, 256>>>(ph, pas0, pad0, prow, pcol, b0, lnw0, lnb0, pbuf);

    // layer 1: GATConv(256 -> 4x64)
    gemm_tc<4><<<ggrid, 256>>>(pbuf, W1, ph, n, 256, as1, ad1, pas1, pad1);
    agg_kernel<4><<<n, 256>>>(ph, pas1, pad1, prow, pcol, b1, lnw1, lnb1, pbuf);

    // layer 2: GATConv(256 -> 1x256)
    gemm_tc<1><<<ggrid, 256>>>(pbuf, W2, ph, n, 256, as2, ad2, pas2, pad2);
    agg_kernel<1><<<n, 256>>>(ph, pas2, pad2, prow, pcol, b2, lnw2, lnb2, out);
}